// round 17
// baseline (speedup 1.0000x reference)
#include <cuda_runtime.h>
#include <cuda_fp16.h>
#include <cstdint>
#include <cstddef>

// ---------------------------------------------------------------------------
// LSTM cell, base-sm_103 ISA (mma.sync path).
// fp16 2-term split (x = hi + lo), 3 products (hi*hi + lo*hi + hi*lo) per
// k-chunk with register-cached fragments.
// R15: B-fragments via ldmatrix.x4 (was 128 scalar LDS/warp/iter),
//      3-stage KC=32 pipeline with ONE __syncthreads per iter,
//      merged conversion prepass (2 launches per call total).
// CTA tile M=128 x N=256 (64 h-cols x 4 gates), warp tile 64x64, 8 warps.
// ---------------------------------------------------------------------------

#define B_DIM   16384
#define K_TOT   2048
#define N_TOT   4096
#define H_DIM   1024
#define KC      32          // k elems per stage
#define NITER   64          // 2048/32
#define NTHREADS 256

#define ROW_BYTES  80       // 64B data + 16B pad; r*80 mod 128 hits 8 distinct
                            // 16B slots per 8 rows -> conflict-free ldmatrix
#define OFF_AHI    0u
#define OFF_ALO    10240u   // 128*80
#define OFF_BHI    20480u
#define OFF_BLO    40960u   // +256*80
#define STAGE_BYTES 61440u
#define G_STRIDE   260      // epilogue fp32 tile stride (128*260*4 = 133120)
#define SMEM_BYTES 184320   // 3 stages; epilogue reuse fits (133120)

// scratch (device globals; no runtime allocation allowed)
__device__ __align__(256) __half g_Ahi[(size_t)B_DIM * K_TOT];
__device__ __align__(256) __half g_Alo[(size_t)B_DIM * K_TOT];
__device__ __align__(256) __half g_Bhi[(size_t)N_TOT * K_TOT];
__device__ __align__(256) __half g_Blo[(size_t)N_TOT * K_TOT];

// ---------------- helpers ----------------
__device__ __forceinline__ uint32_t smem_u32(const void* p) {
    uint32_t a;
    asm("{ .reg .u64 t; cvta.to.shared.u64 t, %1; cvt.u32.u64 %0, t; }"
        : "=r"(a) : "l"(p));
    return a;
}
__device__ __forceinline__ void cp16(uint32_t dst, const void* src) {
    asm volatile("cp.async.cg.shared.global [%0], [%1], 16;" :: "r"(dst), "l"(src));
}
// clamped fast sigmoid/tanh: |g| ~ N(0,45^2) overflows __expf without clamp.
__device__ __forceinline__ float fsigm(float x) {
    x = fminf(fmaxf(x, -30.0f), 30.0f);
    float e = __expf(-x);
    return __fdividef(1.0f, 1.0f + e);
}
__device__ __forceinline__ float ftanh(float x) {
    x = fminf(fmaxf(x, -15.0f), 15.0f);
    float e = __expf(-2.0f * x);
    return __fdividef(1.0f - e, 1.0f + e);
}
__device__ __forceinline__ void ldm_x4(uint32_t* r, uint32_t addr) {
    asm volatile("ldmatrix.sync.aligned.m8n8.x4.shared.b16 {%0,%1,%2,%3}, [%4];"
        : "=r"(r[0]), "=r"(r[1]), "=r"(r[2]), "=r"(r[3]) : "r"(addr));
}
__device__ __forceinline__ void mma16816(float* d, const uint32_t* a, const uint32_t* b) {
    asm volatile(
        "mma.sync.aligned.m16n8k16.row.col.f32.f16.f16.f32 "
        "{%0,%1,%2,%3}, {%4,%5,%6,%7}, {%8,%9}, {%0,%1,%2,%3};"
        : "+f"(d[0]), "+f"(d[1]), "+f"(d[2]), "+f"(d[3])
        : "r"(a[0]), "r"(a[1]), "r"(a[2]), "r"(a[3]), "r"(b[0]), "r"(b[1]));
}

// ---------------- merged conversion prepass (fp32 -> fp16 hi/lo) -----------
#define CVT_A_BLOCKS 8192
#define CVT_B_BLOCKS 2048
__global__ void cvt_kernel(const float* __restrict__ inp, const float* __restrict__ hp,
                           const float* __restrict__ wih, const float* __restrict__ whh)
{
    if (blockIdx.x < CVT_A_BLOCKS) {
        const size_t npair = (size_t)B_DIM * K_TOT / 2;
        for (size_t i = (size_t)blockIdx.x * blockDim.x + threadIdx.x;
             i < npair; i += (size_t)CVT_A_BLOCKS * blockDim.x) {
            size_t e = i * 2;
            int col = (int)(e & (K_TOT - 1));
            size_t r = e >> 11;
            const float* src = (col < H_DIM) ? (inp + (r << 10) + col)
                                             : (hp  + (r << 10) + (col - H_DIM));
            float2 v = *(const float2*)src;
            __half hx = __float2half_rn(v.x), hy = __float2half_rn(v.y);
            float lx = v.x - __half2float(hx);
            float ly = v.y - __half2float(hy);
            *(__half2*)(g_Ahi + e) = __halves2half2(hx, hy);
            *(__half2*)(g_Alo + e) = __halves2half2(__float2half_rn(lx), __float2half_rn(ly));
        }
    } else {
        const size_t npair = (size_t)N_TOT * K_TOT / 2;
        for (size_t i = (size_t)(blockIdx.x - CVT_A_BLOCKS) * blockDim.x + threadIdx.x;
             i < npair; i += (size_t)CVT_B_BLOCKS * blockDim.x) {
            size_t e = i * 2;
            int col = (int)(e & (K_TOT - 1));
            size_t r = e >> 11;
            const float* src = (col < H_DIM) ? (wih + (r << 10) + col)
                                             : (whh + (r << 10) + (col - H_DIM));
            float2 v = *(const float2*)src;
            __half hx = __float2half_rn(v.x), hy = __float2half_rn(v.y);
            float lx = v.x - __half2float(hx);
            float ly = v.y - __half2float(hy);
            *(__half2*)(g_Bhi + e) = __halves2half2(hx, hy);
            *(__half2*)(g_Blo + e) = __halves2half2(__float2half_rn(lx), __float2half_rn(ly));
        }
    }
}

// ---------------- main fused GEMM + LSTM kernel ----------------
__global__ void __launch_bounds__(NTHREADS, 1)
lstm_mma_kernel(const float* __restrict__ c_prev,
                const float* __restrict__ b_ih, const float* __restrict__ b_hh,
                float* __restrict__ out)
{
    extern __shared__ char smem[];
    const int tid  = threadIdx.x;
    const int lane = tid & 31, wid = tid >> 5;
    const int wr = wid >> 2, wc = wid & 3;       // warp 2x4 grid (m,n)
    const int m0 = blockIdx.y * 128;
    const int h0 = blockIdx.x * 64;
    const uint32_t sb = smem_u32(smem);

    float acc[4][8][4];
    #pragma unroll
    for (int a = 0; a < 4; a++)
        #pragma unroll
        for (int b = 0; b < 8; b++)
            #pragma unroll
            for (int c = 0; c < 4; c++) acc[a][b][c] = 0.0f;

    // stage loader: 4 tiles, K=32 chunk. 3072 cp16 / 256 thr = 12 each.
    auto issue_stage = [&](int it) {
        const int kc = it * KC;
        const uint32_t st = sb + (uint32_t)(it % 3) * STAGE_BYTES;
        #pragma unroll
        for (int i = 0; i < 2; i++) {                 // A: 128 rows x 4 segs
            int v = tid + i * NTHREADS;
            int r = v >> 2, seg = v & 3;
            uint32_t d = st + (uint32_t)(r * ROW_BYTES + seg * 16);
            size_t  go = (size_t)(m0 + r) * K_TOT + kc + seg * 8;
            cp16(d + OFF_AHI, g_Ahi + go);
            cp16(d + OFF_ALO, g_Alo + go);
        }
        #pragma unroll
        for (int i = 0; i < 4; i++) {                 // B: 256 gate rows x 4 segs
            int v = tid + i * NTHREADS;
            int r = v >> 2, seg = v & 3;
            int n = ((r >> 6) << 10) + h0 + (r & 63); // gate*1024 + h
            uint32_t d = st + (uint32_t)(r * ROW_BYTES + seg * 16);
            size_t  go = (size_t)n * K_TOT + kc + seg * 8;
            cp16(d + OFF_BHI, g_Bhi + go);
            cp16(d + OFF_BLO, g_Blo + go);
        }
        asm volatile("cp.async.commit_group;" ::: "memory");
    };

    issue_stage(0);
    issue_stage(1);

    // fragment smem addresses (per-lane constants)
    const uint32_t a_lane = (uint32_t)((wr * 64 + (lane & 15)) * ROW_BYTES
                                       + ((lane >> 4) << 4));
    const uint32_t b_lane = (uint32_t)((wc * 64 + ((lane >> 4) & 1) * 8 + (lane & 7)) * ROW_BYTES
                                       + (((lane >> 3) & 1) << 4));

    for (int it = 0; it < NITER; it++) {
        asm volatile("cp.async.wait_group 1;" ::: "memory");
        __syncthreads();
        // buffer (it+2)%3 == (it-1)%3 was consumed at it-1; all warps passed
        // the barrier, so refilling it now is safe. One sync per iteration.
        if (it + 2 < NITER) issue_stage(it + 2);
        else asm volatile("cp.async.commit_group;" ::: "memory");

        const uint32_t st = sb + (uint32_t)(it % 3) * STAGE_BYTES;

        #pragma unroll 1
        for (int ks = 0; ks < 2; ks++) {
            const uint32_t kb = (uint32_t)(ks * 32);
            // --- Ahi + Bhi fragments (each feeds 2 products) ---
            uint32_t ahi[4][4], bhi[4][4];
            #pragma unroll
            for (int mi = 0; mi < 4; mi++)
                ldm_x4(ahi[mi], st + OFF_AHI + a_lane + (uint32_t)(mi * 16 * ROW_BYTES) + kb);
            #pragma unroll
            for (int njp = 0; njp < 4; njp++)
                ldm_x4(bhi[njp], st + OFF_BHI + b_lane + (uint32_t)(njp * 16 * ROW_BYTES) + kb);
            // product 1: hi*hi
            #pragma unroll
            for (int mi = 0; mi < 4; mi++)
                #pragma unroll
                for (int njp = 0; njp < 4; njp++) {
                    mma16816(acc[mi][2 * njp],     ahi[mi], &bhi[njp][0]);
                    mma16816(acc[mi][2 * njp + 1], ahi[mi], &bhi[njp][2]);
                }
            // product 2: lo*hi (reuse bhi)
            {
                uint32_t alo[4][4];
                #pragma unroll
                for (int mi = 0; mi < 4; mi++)
                    ldm_x4(alo[mi], st + OFF_ALO + a_lane + (uint32_t)(mi * 16 * ROW_BYTES) + kb);
                #pragma unroll
                for (int mi = 0; mi < 4; mi++)
                    #pragma unroll
                    for (int njp = 0; njp < 4; njp++) {
                        mma16816(acc[mi][2 * njp],     alo[mi], &bhi[njp][0]);
                        mma16816(acc[mi][2 * njp + 1], alo[mi], &bhi[njp][2]);
                    }
            }
            // product 3: hi*lo (reuse ahi)
            {
                uint32_t blo[4][4];
                #pragma unroll
                for (int njp = 0; njp < 4; njp++)
                    ldm_x4(blo[njp], st + OFF_BLO + b_lane + (uint32_t)(njp * 16 * ROW_BYTES) + kb);
                #pragma unroll
                for (int mi = 0; mi < 4; mi++)
                    #pragma unroll
                    for (int njp = 0; njp < 4; njp++) {
                        mma16816(acc[mi][2 * njp],     ahi[mi], &blo[njp][0]);
                        mma16816(acc[mi][2 * njp + 1], ahi[mi], &blo[njp][2]);
                    }
            }
        }
    }

    // ---- epilogue: restage gates through smem, fused LSTM math ----
    __syncthreads();
    float* g = (float*)smem;
    #pragma unroll
    for (int mi = 0; mi < 4; mi++) {
        int row = wr * 64 + mi * 16 + (lane >> 2);
        #pragma unroll
        for (int nj = 0; nj < 8; nj++) {
            int col = wc * 64 + nj * 8 + (lane & 3) * 2;
            *(float2*)&g[row * G_STRIDE + col] =
                make_float2(acc[mi][nj][0], acc[mi][nj][1]);
            *(float2*)&g[(row + 8) * G_STRIDE + col] =
                make_float2(acc[mi][nj][2], acc[mi][nj][3]);
        }
    }
    __syncthreads();

    for (int idx = tid; idx < 128 * 64; idx += NTHREADS) {
        int m  = idx >> 6, hh = idx & 63;
        int hg = h0 + hh;
        size_t mg = (size_t)(m0 + m);
        float gi = g[m * G_STRIDE + hh]       + b_ih[hg]        + b_hh[hg];
        float gf = g[m * G_STRIDE + 64 + hh]  + b_ih[1024 + hg] + b_hh[1024 + hg];
        float gc = g[m * G_STRIDE + 128 + hh] + b_ih[2048 + hg] + b_hh[2048 + hg];
        float go = g[m * G_STRIDE + 192 + hh] + b_ih[3072 + hg] + b_hh[3072 + hg];
        float ig = fsigm(gi), fg = fsigm(gf), og = fsigm(go);
        float cd = ftanh(gc);
        float cn = c_prev[mg * H_DIM + hg] * fg + ig * cd;
        float hn = ftanh(cn) * og;
        out[mg * H_DIM + hg] = hn;
        out[(size_t)B_DIM * H_DIM + mg * H_DIM + hg] = cn;
    }
}

// ---------------- launch ----------------
extern "C" void kernel_launch(void* const* d_in, const int* in_sizes, int n_in,
                              void* d_out, int out_size) {
    const float* input  = (const float*)d_in[0];
    const float* h_prev = (const float*)d_in[1];
    const float* c_prev = (const float*)d_in[2];
    const float* W_ih   = (const float*)d_in[3];
    const float* W_hh   = (const float*)d_in[4];
    const float* b_ih   = (const float*)d_in[5];
    const float* b_hh   = (const float*)d_in[6];
    float* out = (float*)d_out;

    cvt_kernel<<<CVT_A_BLOCKS + CVT_B_BLOCKS, 256>>>(input, h_prev, W_ih, W_hh);

    cudaFuncSetAttribute(lstm_mma_kernel,
                         cudaFuncAttributeMaxDynamicSharedMemorySize, SMEM_BYTES);
    dim3 grid(16, 128);   // 16 h-groups x 128 m-tiles
    lstm_mma_kernel<<<grid, NTHREADS, SMEM_BYTES>>>(c_prev, b_ih, b_hh, out);
}